// round 15
// baseline (speedup 1.0000x reference)
#include <cuda_runtime.h>
#include <cstdint>
#include <math.h>

#define NF 64
#define Bn 5000
#define Ln 10
#define Tn 25
#define Kn 8

typedef unsigned long long ull;

// u-table [t][b][l][k] (40 MB): gather rows contiguous 32B.
__device__ float g_u[(size_t)Tn * Bn * Ln * Kn];

#define FMA2(d_, a_, b_, c_) \
    asm("fma.rn.f32x2 %0, %1, %2, %3;" : "=l"(d_) : "l"(a_), "l"(b_), "l"(c_))
#define CP_ASYNC16(dst, src) \
    asm volatile("cp.async.cg.shared.global [%0], [%1], 16;" \
                 :: "r"(dst), "l"(src))
#define CP_COMMIT() asm volatile("cp.async.commit_group;")
#define CP_WAIT(n)  asm volatile("cp.async.wait_group %0;" :: "n"(n))

__device__ __forceinline__ ull dupf(float x) {
    unsigned int w = __float_as_uint(x);
    ull q;
    asm("mov.b64 %0, {%1,%2};" : "=l"(q) : "r"(w), "r"(w));
    return q;
}

__device__ __forceinline__ float4 lds128(unsigned int a) {
    float4 v;
    asm volatile("ld.shared.v4.f32 {%0,%1,%2,%3}, [%4];"
                 : "=f"(v.x), "=f"(v.y), "=f"(v.z), "=f"(v.w) : "r"(a));
    return v;
}

#define THREADS 128
#define STAGE_ROWS 128
#define STAGE_BYTES 32768
#define NSTAGE 2
#define SMEM_MAIN (NSTAGE * STAGE_BYTES + 2048)

#define SCAN_BLOCKS 96           // ~traffic-proportional split (80/368 MB)
#define TOTAL_BLOCKS 444

// ---------------------------------------------------------------------------
// K1 (heterogeneous persistent kernel):
//  blocks [0, SCAN_BLOCKS):   chol + AR(1) scan -> g_u   (80 MB stream)
//  blocks [SCAN_BLOCKS, 444): GEMV fixed part  -> out    (288 MB stream)
// The two groups have no data dependency; their DRAM traffic overlaps.
// ---------------------------------------------------------------------------
__global__ void __launch_bounds__(THREADS, 3)
k1_kernel(const float* __restrict__ X,
          const float* __restrict__ beta,
          const float* __restrict__ eps,
          const float* __restrict__ raw_rho,
          const float* __restrict__ Sigma,
          float* __restrict__ out, int N) {
    extern __shared__ char smem[];
    __shared__ float sL[Kn][Ln * Ln];       // chol scratch (scan blocks only)
    __shared__ float4 sd4[Ln][2];

    int tid = threadIdx.x;

    if (blockIdx.x < SCAN_BLOCKS) {
        // ================= SCAN PATH =================
        // parallel Cholesky diag (80 threads; serial over columns only)
        for (int i = tid; i < Kn * Ln * Ln; i += THREADS)
            ((float*)sL)[i] = Sigma[i];
        __syncthreads();

        int mk = tid / Ln;
        int mi = tid % Ln;
        bool act = tid < Kn * Ln;
#pragma unroll
        for (int j = 0; j < Ln; j++) {
            if (act && mi == j) {
                float s = sL[mk][j * Ln + j];
                for (int p = 0; p < j; p++) {
                    float v = sL[mk][j * Ln + p];
                    s -= v * v;
                }
                sL[mk][j * Ln + j] = sqrtf(s);
            }
            __syncthreads();
            if (act && mi > j) {
                float s = sL[mk][mi * Ln + j];
                for (int p = 0; p < j; p++)
                    s -= sL[mk][mi * Ln + p] * sL[mk][j * Ln + p];
                sL[mk][mi * Ln + j] = __fdividef(s, sL[mk][j * Ln + j]);
            }
            __syncthreads();
        }
        if (act) ((float*)sd4)[mi * Kn + mk] = sL[mk][mi * Ln + mi];
        __syncthreads();

        // scan: unit = (chain, kq); grid-stride over 100000 units
        const int UNITS = Bn * Ln * 2;
        const int STRIDE = SCAN_BLOCKS * THREADS;
        float4* ug = (float4*)g_u;
        const int ustride = Bn * Ln * Kn / 4;

        for (int idx = blockIdx.x * THREADS + tid; idx < UNITS; idx += STRIDE) {
            int kq = idx & 1;
            int chain = idx >> 1;
            int l = chain % Ln;

            float4 rr = *(const float4*)(raw_rho + l * Kn + kq * 4);
            float4 rho = make_float4(tanhf(rr.x), tanhf(rr.y),
                                     tanhf(rr.z), tanhf(rr.w));
            float4 d = sd4[l][kq];

            const float4* e = (const float4*)(eps) + (size_t)chain * 50 + kq;
            int uidx = chain * 2 + kq;

            float4 u = __ldcs(&e[0]);
            ug[uidx] = u;
#pragma unroll
            for (int t = 1; t < Tn; t++) {
                float4 ev = __ldcs(&e[t * 2]);
                u.x = fmaf(rho.x, u.x, d.x * ev.x);
                u.y = fmaf(rho.y, u.y, d.y * ev.y);
                u.z = fmaf(rho.z, u.z, d.z * ev.z);
                u.w = fmaf(rho.w, u.w, d.w * ev.w);
                ug[t * ustride + uidx] = u;
            }
        }
        return;
    }

    // ================= GEMV PATH (fixed part only) =================
    unsigned int sbase;
    asm("{ .reg .u64 t0; cvta.to.shared.u64 t0, %1; cvt.u32.u64 %0, t0; }"
        : "=r"(sbase) : "l"(smem));
    unsigned int bbase = sbase + NSTAGE * STAGE_BYTES;

    // beta -> smem
    {
        const ulonglong2* bg = (const ulonglong2*)beta;
        *((ulonglong2*)(smem + NSTAGE * STAGE_BYTES) + tid) = bg[tid];
    }

    int T = (N + STAGE_ROWS - 1) / STAGE_ROWS;
    const int GB = TOTAL_BLOCKS - SCAN_BLOCKS;      // GEMV blocks
    int gb = blockIdx.x - SCAN_BLOCKS;

    auto issue_stage = [&](int slot, int ti) {
        unsigned int stb = sbase + slot * STAGE_BYTES;
#pragma unroll
        for (int j = 0; j < 16; j++) {
            int idx = tid + j * THREADS;
            int rl  = idx >> 4;
            int c   = idx & 15;
            int gn  = ti * STAGE_ROWS + rl;
            if (gn > N - 1) gn = N - 1;
            const float* src = X + (size_t)gn * NF + c * 4;
            unsigned int dst = stb + rl * 256 + ((c ^ (rl & 7)) << 4);
            CP_ASYNC16(dst, src);
        }
    };

    {
        int t0 = gb;
        if (t0 < T) issue_stage(0, t0);
        CP_COMMIT();
    }
    __syncthreads();    // beta visible

    for (int i = 0; ; i++) {
        int ti = gb + i * GB;
        if (ti >= T) break;
        int slot = i & 1;

        if (i > 0) __syncthreads();
        int tif = gb + (i + 1) * GB;
        if (tif < T) issue_stage(slot ^ 1, tif);
        CP_COMMIT();

        CP_WAIT(1);
        __syncthreads();

        unsigned int rb = sbase + slot * STAGE_BYTES + tid * 256;
        int rsw = tid & 7;
        ull a0 = 0, a1 = 0, a2 = 0, a3 = 0;
#pragma unroll
        for (int cc = 0; cc < 16; cc++) {
            float4 xv = lds128(rb + ((cc ^ rsw) << 4));
            float xs[4] = {xv.x, xv.y, xv.z, xv.w};
#pragma unroll
            for (int r = 0; r < 4; r++) {
                int j = cc * 4 + r;
                ull q = dupf(xs[r]);
                unsigned int ba = bbase + j * 32;
                ull b0, b1, b2, b3;
                asm volatile("ld.shared.v2.u64 {%0,%1}, [%2];"
                             : "=l"(b0), "=l"(b1) : "r"(ba));
                asm volatile("ld.shared.v2.u64 {%0,%1}, [%2];"
                             : "=l"(b2), "=l"(b3) : "r"(ba + 16));
                FMA2(a0, q, b0, a0);
                FMA2(a1, q, b1, a1);
                FMA2(a2, q, b2, a2);
                FMA2(a3, q, b3, a3);
            }
        }

        int n = ti * STAGE_ROWS + tid;
        if (n < N) {
            float f0, f1, f2, f3, f4, f5, f6, f7;
            asm("mov.b64 {%0,%1}, %2;" : "=f"(f0), "=f"(f1) : "l"(a0));
            asm("mov.b64 {%0,%1}, %2;" : "=f"(f2), "=f"(f3) : "l"(a1));
            asm("mov.b64 {%0,%1}, %2;" : "=f"(f4), "=f"(f5) : "l"(a2));
            asm("mov.b64 {%0,%1}, %2;" : "=f"(f6), "=f"(f7) : "l"(a3));
            float4* op = (float4*)(out + (size_t)n * Kn);
            op[0] = make_float4(f0, f1, f2, f3);   // default policy: may
            op[1] = make_float4(f4, f5, f6, f7);   // survive in L2 for K2
        }
    }
    CP_WAIT(0);
}

// ---------------------------------------------------------------------------
// K2: out[n,:] += u[off[n],:]   (ids + out streams; u random gather)
// ---------------------------------------------------------------------------
__global__ void __launch_bounds__(256)
add_kernel(const int* __restrict__ batter_ids,
           const int* __restrict__ league_ids,
           const int* __restrict__ season_ids,
           float* __restrict__ out, int N) {
    int n = blockIdx.x * 256 + threadIdx.x;
    if (n >= N) return;
    int off = ((season_ids[n] * Bn + batter_ids[n]) * Ln +
               league_ids[n]) * Kn;
    const float4* up = (const float4*)(g_u + off);
    float4 u0 = up[0];
    float4 u1 = up[1];
    float4* op = (float4*)(out + (size_t)n * Kn);
    float4 o0 = op[0];
    float4 o1 = op[1];
    o0.x += u0.x; o0.y += u0.y; o0.z += u0.z; o0.w += u0.w;
    o1.x += u1.x; o1.y += u1.y; o1.z += u1.z; o1.w += u1.w;
    __stcs(&op[0], o0);
    __stcs(&op[1], o1);
}

// ---------------------------------------------------------------------------
extern "C" void kernel_launch(void* const* d_in, const int* in_sizes, int n_in,
                              void* d_out, int out_size) {
    const float* X       = (const float*)d_in[0];
    const int*   bid     = (const int*)d_in[1];
    const int*   lid     = (const int*)d_in[2];
    const int*   sid     = (const int*)d_in[3];
    const float* beta    = (const float*)d_in[4];
    const float* raw_rho = (const float*)d_in[5];
    const float* Sigma   = (const float*)d_in[6];
    const float* eps     = (const float*)d_in[7];
    float*       out     = (float*)d_out;

    const int N = in_sizes[1];

    static int smem_set = 0;
    if (!smem_set) {
        cudaFuncSetAttribute(k1_kernel,
                             cudaFuncAttributeMaxDynamicSharedMemorySize,
                             SMEM_MAIN);
        smem_set = 1;
    }

    k1_kernel<<<TOTAL_BLOCKS, THREADS, SMEM_MAIN>>>(
        X, beta, eps, raw_rho, Sigma, out, N);

    add_kernel<<<(N + 255) / 256, 256>>>(bid, lid, sid, out, N);
}

// round 16
// speedup vs baseline: 1.6581x; 1.6581x over previous
#include <cuda_runtime.h>
#include <cstdint>
#include <math.h>

#define NF 64
#define Bn 5000
#define Ln 10
#define Tn 25
#define Kn 8

typedef unsigned long long ull;

// u-table [t][b][l][k] (40 MB): gather rows contiguous 32B.
__device__ float g_u[(size_t)Tn * Bn * Ln * Kn];

// ---------------------------------------------------------------------------
// pre_kernel (side-stream branch): chol (parallel, 80 threads) + AR(1) scan.
// 128 threads/block, small footprint (no big smem) so blocks co-schedule
// beside the persistent GEMV blocks. One (chain,kq) unit per thread.
// ---------------------------------------------------------------------------
__global__ void __launch_bounds__(128)
pre_kernel(const float* __restrict__ eps, const float* __restrict__ raw_rho,
           const float* __restrict__ Sigma) {
    __shared__ float sL[Kn][Ln * Ln];
    __shared__ float4 sd4[Ln][2];

    int tid = threadIdx.x;

    for (int i = tid; i < Kn * Ln * Ln; i += 128)
        ((float*)sL)[i] = Sigma[i];
    __syncthreads();

    int mk = tid / Ln;
    int mi = tid % Ln;
    bool act = tid < Kn * Ln;
#pragma unroll
    for (int j = 0; j < Ln; j++) {
        if (act && mi == j) {
            float s = sL[mk][j * Ln + j];
            for (int p = 0; p < j; p++) {
                float v = sL[mk][j * Ln + p];
                s -= v * v;
            }
            sL[mk][j * Ln + j] = sqrtf(s);
        }
        __syncthreads();
        if (act && mi > j) {
            float s = sL[mk][mi * Ln + j];
            for (int p = 0; p < j; p++)
                s -= sL[mk][mi * Ln + p] * sL[mk][j * Ln + p];
            sL[mk][mi * Ln + j] = __fdividef(s, sL[mk][j * Ln + j]);
        }
        __syncthreads();
    }
    if (act) ((float*)sd4)[mi * Kn + mk] = sL[mk][mi * Ln + mi];
    __syncthreads();

    int idx = blockIdx.x * 128 + tid;            // (chain, kq)
    if (idx >= Bn * Ln * 2) return;
    int kq = idx & 1;
    int chain = idx >> 1;
    int l = chain % Ln;

    float4 rr = *(const float4*)(raw_rho + l * Kn + kq * 4);
    float4 rho = make_float4(tanhf(rr.x), tanhf(rr.y), tanhf(rr.z), tanhf(rr.w));
    float4 d = sd4[l][kq];

    const float4* e = (const float4*)(eps) + (size_t)chain * 50 + kq;
    float4* ug = (float4*)g_u;
    const int ustride = Bn * Ln * Kn / 4;
    int uidx = chain * 2 + kq;

    float4 u = __ldcs(&e[0]);
    ug[uidx] = u;
#pragma unroll
    for (int t = 1; t < Tn; t++) {
        float4 ev = __ldcs(&e[t * 2]);
        u.x = fmaf(rho.x, u.x, d.x * ev.x);
        u.y = fmaf(rho.y, u.y, d.y * ev.y);
        u.z = fmaf(rho.z, u.z, d.z * ev.z);
        u.w = fmaf(rho.w, u.w, d.w * ev.w);
        ug[t * ustride + uidx] = u;
    }
}

// ---------------------------------------------------------------------------
// fixed_kernel (main-stream branch): out[n,:] = X[n,:] @ beta  (fixed only).
// Persistent cp.async double-buffer, thread-per-row (R13 proven structure).
// Grid 296 = 2 blocks/SM, leaving capacity for pre blocks to co-schedule.
// ---------------------------------------------------------------------------
#define FMA2(d_, a_, b_, c_) \
    asm("fma.rn.f32x2 %0, %1, %2, %3;" : "=l"(d_) : "l"(a_), "l"(b_), "l"(c_))
#define CP_ASYNC16(dst, src) \
    asm volatile("cp.async.cg.shared.global [%0], [%1], 16;" \
                 :: "r"(dst), "l"(src))
#define CP_COMMIT() asm volatile("cp.async.commit_group;")
#define CP_WAIT(n)  asm volatile("cp.async.wait_group %0;" :: "n"(n))

__device__ __forceinline__ ull dupf(float x) {
    unsigned int w = __float_as_uint(x);
    ull q;
    asm("mov.b64 %0, {%1,%2};" : "=l"(q) : "r"(w), "r"(w));
    return q;
}

__device__ __forceinline__ float4 lds128(unsigned int a) {
    float4 v;
    asm volatile("ld.shared.v4.f32 {%0,%1,%2,%3}, [%4];"
                 : "=f"(v.x), "=f"(v.y), "=f"(v.z), "=f"(v.w) : "r"(a));
    return v;
}

#define THREADS 128
#define STAGE_ROWS 128
#define STAGE_BYTES 32768
#define NSTAGE 2
#define SMEM_MAIN (NSTAGE * STAGE_BYTES + 2048)

__global__ void __launch_bounds__(THREADS, 2)
fixed_kernel(const float* __restrict__ X,
             const float* __restrict__ beta,
             float* __restrict__ out, int N) {
    extern __shared__ char smem[];
    unsigned int sbase;
    asm("{ .reg .u64 t0; cvta.to.shared.u64 t0, %1; cvt.u32.u64 %0, t0; }"
        : "=r"(sbase) : "l"(smem));
    unsigned int bbase = sbase + NSTAGE * STAGE_BYTES;

    int tid = threadIdx.x;

    // beta -> smem
    {
        const ulonglong2* bg = (const ulonglong2*)beta;
        *((ulonglong2*)(smem + NSTAGE * STAGE_BYTES) + tid) = bg[tid];
    }

    int T = (N + STAGE_ROWS - 1) / STAGE_ROWS;
    int GRID = gridDim.x;

    auto issue_stage = [&](int slot, int ti) {
        unsigned int stb = sbase + slot * STAGE_BYTES;
#pragma unroll
        for (int j = 0; j < 16; j++) {
            int idx = tid + j * THREADS;
            int rl  = idx >> 4;
            int c   = idx & 15;
            int gn  = ti * STAGE_ROWS + rl;
            if (gn > N - 1) gn = N - 1;
            const float* src = X + (size_t)gn * NF + c * 4;
            unsigned int dst = stb + rl * 256 + ((c ^ (rl & 7)) << 4);
            CP_ASYNC16(dst, src);
        }
    };

    {
        int t0 = blockIdx.x;
        if (t0 < T) issue_stage(0, t0);
        CP_COMMIT();
    }
    __syncthreads();    // beta visible

    for (int i = 0; ; i++) {
        int ti = blockIdx.x + i * GRID;
        if (ti >= T) break;
        int slot = i & 1;

        if (i > 0) __syncthreads();
        int tif = blockIdx.x + (i + 1) * GRID;
        if (tif < T) issue_stage(slot ^ 1, tif);
        CP_COMMIT();

        CP_WAIT(1);
        __syncthreads();

        unsigned int rb = sbase + slot * STAGE_BYTES + tid * 256;
        int rsw = tid & 7;
        ull a0 = 0, a1 = 0, a2 = 0, a3 = 0;
#pragma unroll
        for (int cc = 0; cc < 16; cc++) {
            float4 xv = lds128(rb + ((cc ^ rsw) << 4));
            float xs[4] = {xv.x, xv.y, xv.z, xv.w};
#pragma unroll
            for (int r = 0; r < 4; r++) {
                int j = cc * 4 + r;
                ull q = dupf(xs[r]);
                unsigned int ba = bbase + j * 32;
                ull b0, b1, b2, b3;
                asm volatile("ld.shared.v2.u64 {%0,%1}, [%2];"
                             : "=l"(b0), "=l"(b1) : "r"(ba));
                asm volatile("ld.shared.v2.u64 {%0,%1}, [%2];"
                             : "=l"(b2), "=l"(b3) : "r"(ba + 16));
                FMA2(a0, q, b0, a0);
                FMA2(a1, q, b1, a1);
                FMA2(a2, q, b2, a2);
                FMA2(a3, q, b3, a3);
            }
        }

        int n = ti * STAGE_ROWS + tid;
        if (n < N) {
            float f0, f1, f2, f3, f4, f5, f6, f7;
            asm("mov.b64 {%0,%1}, %2;" : "=f"(f0), "=f"(f1) : "l"(a0));
            asm("mov.b64 {%0,%1}, %2;" : "=f"(f2), "=f"(f3) : "l"(a1));
            asm("mov.b64 {%0,%1}, %2;" : "=f"(f4), "=f"(f5) : "l"(a2));
            asm("mov.b64 {%0,%1}, %2;" : "=f"(f6), "=f"(f7) : "l"(a3));
            float4* op = (float4*)(out + (size_t)n * Kn);
            op[0] = make_float4(f0, f1, f2, f3);
            op[1] = make_float4(f4, f5, f6, f7);
        }
    }
    CP_WAIT(0);
}

// ---------------------------------------------------------------------------
// add_kernel (join): out[n,:] += u[off[n],:]
// ---------------------------------------------------------------------------
__global__ void __launch_bounds__(256)
add_kernel(const int* __restrict__ batter_ids,
           const int* __restrict__ league_ids,
           const int* __restrict__ season_ids,
           float* __restrict__ out, int N) {
    int n = blockIdx.x * 256 + threadIdx.x;
    if (n >= N) return;
    int off = ((season_ids[n] * Bn + batter_ids[n]) * Ln +
               league_ids[n]) * Kn;
    const float4* up = (const float4*)(g_u + off);
    float4 u0 = up[0];
    float4 u1 = up[1];
    float4* op = (float4*)(out + (size_t)n * Kn);
    float4 o0 = op[0];
    float4 o1 = op[1];
    o0.x += u0.x; o0.y += u0.y; o0.z += u0.z; o0.w += u0.w;
    o1.x += u1.x; o1.y += u1.y; o1.z += u1.z; o1.w += u1.w;
    __stcs(&op[0], o0);
    __stcs(&op[1], o1);
}

// ---------------------------------------------------------------------------
// Launch with a forked side stream (graph-capturable: event fork/join makes
// pre_kernel a parallel branch that overlaps with fixed_kernel).
// ---------------------------------------------------------------------------
extern "C" void kernel_launch(void* const* d_in, const int* in_sizes, int n_in,
                              void* d_out, int out_size) {
    const float* X       = (const float*)d_in[0];
    const int*   bid     = (const int*)d_in[1];
    const int*   lid     = (const int*)d_in[2];
    const int*   sid     = (const int*)d_in[3];
    const float* beta    = (const float*)d_in[4];
    const float* raw_rho = (const float*)d_in[5];
    const float* Sigma   = (const float*)d_in[6];
    const float* eps     = (const float*)d_in[7];
    float*       out     = (float*)d_out;

    const int N = in_sizes[1];

    static int inited = 0;
    static cudaStream_t s_side;
    static cudaEvent_t evFork, evJoin;
    if (!inited) {
        cudaFuncSetAttribute(fixed_kernel,
                             cudaFuncAttributeMaxDynamicSharedMemorySize,
                             SMEM_MAIN);
        cudaStreamCreateWithFlags(&s_side, cudaStreamNonBlocking);
        cudaEventCreateWithFlags(&evFork, cudaEventDisableTiming);
        cudaEventCreateWithFlags(&evJoin, cudaEventDisableTiming);
        inited = 1;
    }

    // Fork: side stream runs pre (scan) concurrently with fixed (GEMV).
    cudaEventRecord(evFork, 0);
    cudaStreamWaitEvent(s_side, evFork, 0);

    int units = Bn * Ln * 2;
    pre_kernel<<<(units + 127) / 128, 128, 0, s_side>>>(eps, raw_rho, Sigma);
    cudaEventRecord(evJoin, s_side);

    // Main branch: fixed-effects GEMV (2 blocks/SM so pre can co-schedule).
    fixed_kernel<<<296, THREADS, SMEM_MAIN>>>(X, beta, out, N);

    // Join: add random effects.
    cudaStreamWaitEvent(0, evJoin, 0);
    add_kernel<<<(N + 255) / 256, 256>>>(bid, lid, sid, out, N);
}

// round 17
// speedup vs baseline: 2.1290x; 1.2840x over previous
#include <cuda_runtime.h>
#include <cstdint>
#include <math.h>

#define NF 64
#define Bn 5000
#define Ln 10
#define Tn 25
#define Kn 8

typedef unsigned long long ull;

// u-table [t][b][l][k] (40 MB): gather rows contiguous 32B.
__device__ float g_u[(size_t)Tn * Bn * Ln * Kn];

// ---------------------------------------------------------------------------
// pre_kernel: warp-parallel Cholesky (shfl, no block syncs) + AR(1) scan
// with an 8-deep register prefetch pipeline on the eps stream.
// Thread = (chain, kq); 128 threads/block; grid = one wave (782 blocks).
// ---------------------------------------------------------------------------
__global__ void __launch_bounds__(128)
pre_kernel(const float* __restrict__ eps, const float* __restrict__ raw_rho,
           const float* __restrict__ Sigma) {
    __shared__ float4 sd4[Ln][2];     // chol diag, [l][kq]

    int tid  = threadIdx.x;
    int w    = tid >> 5;              // warp 0..3
    int lane = tid & 31;
    int grp  = lane >> 4;             // 16-lane half: matrix select
    int r    = lane & 15;             // row within matrix (0..9 active)
    int q    = 2 * w + grp;           // matrix index 0..7

    // ---- warp chol: lanes r=0..9 hold row r of matrix q in registers ----
    {
        float a[Ln];
        if (r < Ln) {
#pragma unroll
            for (int p = 0; p < Ln; p++)
                a[p] = __ldg(&Sigma[q * Ln * Ln + r * Ln + p]);
        } else {
#pragma unroll
            for (int p = 0; p < Ln; p++) a[p] = 1.0f;  // benign dummy
        }

#pragma unroll
        for (int j = 0; j < Ln; j++) {
            // diag from lane j of this 16-group (a[j] fully updated there)
            float djj = sqrtf(__shfl_sync(0xffffffffu, a[j], grp * 16 + j, 32));
            float inv = __fdividef(1.0f, djj);
            if (r == j) a[j] = djj;
            else if (r > j && r < Ln) a[j] *= inv;   // L_rj
            float Lij = a[j];
            // trailing update: a[p] -= L_rj * L_pj  (L_pj lives on lane p)
#pragma unroll
            for (int p = j + 1; p < Ln; p++) {
                float Lpj = __shfl_sync(0xffffffffu, a[j], grp * 16 + p, 32);
                if (r >= p && r < Ln) a[p] -= Lij * Lpj;
            }
        }
        if (r < Ln) ((float*)sd4)[r * Kn + q] = a[r];  // d[l=r][k=q]
    }
    __syncthreads();

    // ---- scan with 8-deep prefetch ----
    int idx = blockIdx.x * 128 + tid;            // (chain, kq)
    if (idx >= Bn * Ln * 2) return;
    int kq = idx & 1;
    int chain = idx >> 1;
    int l = chain % Ln;

    float4 rr = *(const float4*)(raw_rho + l * Kn + kq * 4);
    float4 rho = make_float4(tanhf(rr.x), tanhf(rr.y), tanhf(rr.z), tanhf(rr.w));
    float4 d = sd4[l][kq];

    const float4* e = (const float4*)(eps) + (size_t)chain * 50 + kq;
    float4* ug = (float4*)g_u;
    const int ustride = Bn * Ln * Kn / 4;
    int uidx = chain * 2 + kq;

    float4 buf[8];
#pragma unroll
    for (int t = 0; t < 8; t++) buf[t] = __ldcs(&e[t * 2]);

    float4 u = buf[0];
    ug[uidx] = u;
#pragma unroll
    for (int t = 1; t < Tn; t++) {
        float4 ev = buf[t & 7];
        if (t + 7 < Tn) buf[(t + 7) & 7] = __ldcs(&e[(t + 7) * 2]);
        u.x = fmaf(rho.x, u.x, d.x * ev.x);
        u.y = fmaf(rho.y, u.y, d.y * ev.y);
        u.z = fmaf(rho.z, u.z, d.z * ev.z);
        u.w = fmaf(rho.w, u.w, d.w * ev.w);
        ug[t * ustride + uidx] = u;
    }
}

// ---------------------------------------------------------------------------
// main_kernel (R13 proven, verbatim): persistent cp.async double-buffer,
// thread-per-row GEMV + fused L2 u-gather.
//   out[n,:] = X[n,:] @ beta + u[((s*Bn+b)*Ln+l)*Kn]
// ---------------------------------------------------------------------------
#define FMA2(d_, a_, b_, c_) \
    asm("fma.rn.f32x2 %0, %1, %2, %3;" : "=l"(d_) : "l"(a_), "l"(b_), "l"(c_))
#define CP_ASYNC16(dst, src) \
    asm volatile("cp.async.cg.shared.global [%0], [%1], 16;" \
                 :: "r"(dst), "l"(src))
#define CP_COMMIT() asm volatile("cp.async.commit_group;")
#define CP_WAIT(n)  asm volatile("cp.async.wait_group %0;" :: "n"(n))

__device__ __forceinline__ ull dupf(float x) {
    unsigned int w = __float_as_uint(x);
    ull q;
    asm("mov.b64 %0, {%1,%2};" : "=l"(q) : "r"(w), "r"(w));
    return q;
}

__device__ __forceinline__ float4 lds128(unsigned int a) {
    float4 v;
    asm volatile("ld.shared.v4.f32 {%0,%1,%2,%3}, [%4];"
                 : "=f"(v.x), "=f"(v.y), "=f"(v.z), "=f"(v.w) : "r"(a));
    return v;
}

#define THREADS 128
#define STAGE_ROWS 128
#define STAGE_BYTES 32768
#define NSTAGE 2
#define SMEM_MAIN (NSTAGE * STAGE_BYTES + 2048)

__global__ void __launch_bounds__(THREADS, 3)
main_kernel(const float* __restrict__ X,
            const int* __restrict__ batter_ids,
            const int* __restrict__ league_ids,
            const int* __restrict__ season_ids,
            const float* __restrict__ beta,
            float* __restrict__ out, int N) {
    extern __shared__ char smem[];
    unsigned int sbase;
    asm("{ .reg .u64 t0; cvta.to.shared.u64 t0, %1; cvt.u32.u64 %0, t0; }"
        : "=r"(sbase) : "l"(smem));
    unsigned int bbase = sbase + NSTAGE * STAGE_BYTES;

    int tid = threadIdx.x;

    // beta -> smem
    {
        const ulonglong2* bg = (const ulonglong2*)beta;
        *((ulonglong2*)(smem + NSTAGE * STAGE_BYTES) + tid) = bg[tid];
    }

    int T = (N + STAGE_ROWS - 1) / STAGE_ROWS;
    int GRID = gridDim.x;

    auto issue_stage = [&](int slot, int ti) {
        unsigned int stb = sbase + slot * STAGE_BYTES;
#pragma unroll
        for (int j = 0; j < 16; j++) {
            int idx = tid + j * THREADS;
            int rl  = idx >> 4;
            int c   = idx & 15;
            int gn  = ti * STAGE_ROWS + rl;
            if (gn > N - 1) gn = N - 1;
            const float* src = X + (size_t)gn * NF + c * 4;
            unsigned int dst = stb + rl * 256 + ((c ^ (rl & 7)) << 4);
            CP_ASYNC16(dst, src);
        }
    };

    {
        int t0 = blockIdx.x;
        if (t0 < T) issue_stage(0, t0);
        CP_COMMIT();
    }
    int offA;
    {
        int n0 = min(blockIdx.x * STAGE_ROWS + tid, N - 1);
        offA = ((season_ids[n0] * Bn + batter_ids[n0]) * Ln +
                league_ids[n0]) * Kn;
    }
    __syncthreads();    // beta visible

    for (int i = 0; ; i++) {
        int ti = blockIdx.x + i * GRID;
        if (ti >= T) break;
        int slot = i & 1;

        if (i > 0) __syncthreads();
        int tif = blockIdx.x + (i + 1) * GRID;
        if (tif < T) issue_stage(slot ^ 1, tif);
        CP_COMMIT();

        const float4* up = (const float4*)(g_u + offA);
        float4 u0 = up[0];
        float4 u1 = up[1];
        {
            int tin = min(blockIdx.x + (i + 1) * GRID, T - 1);
            int nn = min(tin * STAGE_ROWS + tid, N - 1);
            offA = ((season_ids[nn] * Bn + batter_ids[nn]) * Ln +
                    league_ids[nn]) * Kn;
        }

        CP_WAIT(1);
        __syncthreads();

        unsigned int rb = sbase + slot * STAGE_BYTES + tid * 256;
        int rsw = tid & 7;
        ull a0 = 0, a1 = 0, a2 = 0, a3 = 0;
#pragma unroll
        for (int cc = 0; cc < 16; cc++) {
            float4 xv = lds128(rb + ((cc ^ rsw) << 4));
            float xs[4] = {xv.x, xv.y, xv.z, xv.w};
#pragma unroll
            for (int r = 0; r < 4; r++) {
                int j = cc * 4 + r;
                ull q = dupf(xs[r]);
                unsigned int ba = bbase + j * 32;
                ull b0, b1, b2, b3;
                asm volatile("ld.shared.v2.u64 {%0,%1}, [%2];"
                             : "=l"(b0), "=l"(b1) : "r"(ba));
                asm volatile("ld.shared.v2.u64 {%0,%1}, [%2];"
                             : "=l"(b2), "=l"(b3) : "r"(ba + 16));
                FMA2(a0, q, b0, a0);
                FMA2(a1, q, b1, a1);
                FMA2(a2, q, b2, a2);
                FMA2(a3, q, b3, a3);
            }
        }

        int n = ti * STAGE_ROWS + tid;
        if (n < N) {
            float f0, f1, f2, f3, f4, f5, f6, f7;
            asm("mov.b64 {%0,%1}, %2;" : "=f"(f0), "=f"(f1) : "l"(a0));
            asm("mov.b64 {%0,%1}, %2;" : "=f"(f2), "=f"(f3) : "l"(a1));
            asm("mov.b64 {%0,%1}, %2;" : "=f"(f4), "=f"(f5) : "l"(a2));
            asm("mov.b64 {%0,%1}, %2;" : "=f"(f6), "=f"(f7) : "l"(a3));
            float4 o0 = make_float4(f0 + u0.x, f1 + u0.y, f2 + u0.z, f3 + u0.w);
            float4 o1 = make_float4(f4 + u1.x, f5 + u1.y, f6 + u1.z, f7 + u1.w);
            float4* op = (float4*)(out + (size_t)n * Kn);
            __stcs(&op[0], o0);
            __stcs(&op[1], o1);
        }
    }
    CP_WAIT(0);
}

// ---------------------------------------------------------------------------
extern "C" void kernel_launch(void* const* d_in, const int* in_sizes, int n_in,
                              void* d_out, int out_size) {
    const float* X       = (const float*)d_in[0];
    const int*   bid     = (const int*)d_in[1];
    const int*   lid     = (const int*)d_in[2];
    const int*   sid     = (const int*)d_in[3];
    const float* beta    = (const float*)d_in[4];
    const float* raw_rho = (const float*)d_in[5];
    const float* Sigma   = (const float*)d_in[6];
    const float* eps     = (const float*)d_in[7];
    float*       out     = (float*)d_out;

    const int N = in_sizes[1];

    static int smem_set = 0;
    if (!smem_set) {
        cudaFuncSetAttribute(main_kernel,
                             cudaFuncAttributeMaxDynamicSharedMemorySize,
                             SMEM_MAIN);
        smem_set = 1;
    }

    int units = Bn * Ln * 2;
    pre_kernel<<<(units + 127) / 128, 128>>>(eps, raw_rho, Sigma);

    main_kernel<<<444, THREADS, SMEM_MAIN>>>(X, bid, lid, sid, beta, out, N);
}